// round 4
// baseline (speedup 1.0000x reference)
#include <cuda_runtime.h>
#include <math.h>

// Problem constants
#define BATCH   16384
#define TSTEPS  28
#define FEAT    28
#define HID     128
#define G3      384     // 3*HID
#define NCLS    10

#define TILE_B  64
#define NTHREADS 512
#define KC      16      // R streaming chunk (rows of k)

// SMEM layout (floats):
//   h_s : [HID][TILE_B]          = 8192
//   W_s : [FEAT][G3]             = 10752
//   x_s : [FEAT][TILE_B]         = 1792
//   R_s : 2 x [KC][G3]           = 12288 (double buffered)
#define SM_FLOATS (HID*TILE_B + FEAT*G3 + FEAT*TILE_B + 2*KC*G3)
#define SM_BYTES  (SM_FLOATS * 4)

typedef unsigned long long u64;

__device__ __forceinline__ float sigmoidf_(float v) {
    return 1.0f / (1.0f + __expf(-v));
}

// packed dual-fp32 FMA: d = a * b + d   (Blackwell f32x2 path, 2 FLOPs/slot*2)
__device__ __forceinline__ void fma2(u64& d, u64 a, u64 b) {
    asm("fma.rn.f32x2 %0, %1, %2, %0;" : "+l"(d) : "l"(a), "l"(b));
}

// broadcast one fp32 into both halves of a 64-bit packed register
__device__ __forceinline__ u64 bcast2(float v) {
    u64 r;
    asm("mov.b64 %0, {%1, %1};" : "=l"(r) : "f"(v));
    return r;
}

__device__ __forceinline__ float2 unpack2(u64 v) {
    float2 r;
    asm("mov.b64 {%0, %1}, %2;" : "=f"(r.x), "=f"(r.y) : "l"(v));
    return r;
}

__global__ __launch_bounds__(NTHREADS, 1)
void gru_fused_kernel(const float* __restrict__ x,      // (B,T,F,1)
                      const float* __restrict__ Wk,     // (F,3H)
                      const float* __restrict__ Rk,     // (H,3H)
                      const float* __restrict__ bias,   // (2,3H)
                      const float* __restrict__ dw,     // (H,C)
                      const float* __restrict__ db,     // (C)
                      float* __restrict__ out)          // (B,C)
{
    extern __shared__ float sm[];
    float* h_s = sm;                          // h_s[j*TILE_B + row]
    float* W_s = h_s + HID * TILE_B;          // W_s[k*G3 + c]
    float* x_s = W_s + FEAT * G3;             // x_s[f*TILE_B + row]
    float* R_s = x_s + FEAT * TILE_B;         // 2 buffers of [KC][G3]

    const int tid = threadIdx.x;
    const int rg  = tid & 15;                 // 16 row groups * 4 rows = 64 rows
    const int cg  = tid >> 4;                 // 32 col groups * 4 cols = 128 h-cols
    const int r0  = rg * 4;
    const int j0  = cg * 4;
    const int b0  = blockIdx.x * TILE_B;

    for (int i = tid; i < FEAT * G3; i += NTHREADS) W_s[i] = Wk[i];
    for (int i = tid; i < HID * TILE_B; i += NTHREADS) h_s[i] = 0.0f;

    // Per-thread gate biases for cols j0..j0+3
    float bz[4], brg[4], bxh[4], brh[4];
#pragma unroll
    for (int c = 0; c < 4; c++) {
        bz[c]  = bias[j0 + c]            + bias[G3 + j0 + c];
        brg[c] = bias[HID + j0 + c]      + bias[G3 + HID + j0 + c];
        bxh[c] = bias[2*HID + j0 + c];
        brh[c] = bias[G3 + 2*HID + j0 + c];
    }

    __syncthreads();

    for (int t = 0; t < TSTEPS; t++) {
        // Stage x tile (transposed): x_s[f][row] = x[b0+row][t][f]
        for (int i = tid; i < FEAT * TILE_B; i += NTHREADS) {
            int row = i / FEAT;
            int f   = i % FEAT;
            x_s[f * TILE_B + row] =
                x[(size_t)(b0 + row) * (TSTEPS * FEAT) + t * FEAT + f];
        }
        // Stage R chunk 0 into buffer 0
        for (int i = tid; i < KC * G3; i += NTHREADS) R_s[i] = Rk[i];
        __syncthreads();   // x_s + R chunk0 ready; prev-step h writes ordered

        // Accumulators: [4 rows][2 col-pairs], packed fp32x2 across adjacent cols
        u64 az[4][2], ar[4][2], ah[4][2], axh[4][2];
#pragma unroll
        for (int rr = 0; rr < 4; rr++)
#pragma unroll
            for (int p = 0; p < 2; p++) {
                az[rr][p] = 0ull; ar[rr][p] = 0ull;
                ah[rr][p] = 0ull; axh[rr][p] = 0ull;
            }

        // ---- Input projection: K = 28 over (x_s, W_s) ----
#pragma unroll 4
        for (int k = 0; k < FEAT; k++) {
            float4 af = *(const float4*)&x_s[k * TILE_B + r0];
            u64 a[4] = {bcast2(af.x), bcast2(af.y), bcast2(af.z), bcast2(af.w)};
            ulonglong2 v0 = *(const ulonglong2*)&W_s[k * G3 + j0];
            ulonglong2 v1 = *(const ulonglong2*)&W_s[k * G3 + HID + j0];
            ulonglong2 v2 = *(const ulonglong2*)&W_s[k * G3 + 2*HID + j0];
#pragma unroll
            for (int rr = 0; rr < 4; rr++) {
                fma2(az[rr][0],  a[rr], v0.x); fma2(az[rr][1],  a[rr], v0.y);
                fma2(ar[rr][0],  a[rr], v1.x); fma2(ar[rr][1],  a[rr], v1.y);
                fma2(axh[rr][0], a[rr], v2.x); fma2(axh[rr][1], a[rr], v2.y);
            }
        }

        // ---- Recurrent projection: K = 128, R double-buffered in SMEM ----
        for (int ch = 0; ch < HID / KC; ch++) {
            float* cur = R_s + (ch & 1) * (KC * G3);
            float* nxt = R_s + ((ch + 1) & 1) * (KC * G3);

            // Prefetch next chunk into registers (latency hidden by compute)
            float4 pr0, pr1, pr2;
            if (ch < HID / KC - 1) {
                const float* src = Rk + (ch + 1) * KC * G3;
                pr0 = *(const float4*)&src[0 * 2048 + tid * 4];
                pr1 = *(const float4*)&src[1 * 2048 + tid * 4];
                pr2 = *(const float4*)&src[2 * 2048 + tid * 4];
            }

#pragma unroll 4
            for (int kk = 0; kk < KC; kk++) {
                int k = ch * KC + kk;
                float4 af = *(const float4*)&h_s[k * TILE_B + r0];
                u64 a[4] = {bcast2(af.x), bcast2(af.y), bcast2(af.z), bcast2(af.w)};
                ulonglong2 v0 = *(const ulonglong2*)&cur[kk * G3 + j0];
                ulonglong2 v1 = *(const ulonglong2*)&cur[kk * G3 + HID + j0];
                ulonglong2 v2 = *(const ulonglong2*)&cur[kk * G3 + 2*HID + j0];
#pragma unroll
                for (int rr = 0; rr < 4; rr++) {
                    fma2(az[rr][0], a[rr], v0.x); fma2(az[rr][1], a[rr], v0.y);
                    fma2(ar[rr][0], a[rr], v1.x); fma2(ar[rr][1], a[rr], v1.y);
                    fma2(ah[rr][0], a[rr], v2.x); fma2(ah[rr][1], a[rr], v2.y);
                }
            }

            if (ch < HID / KC - 1) {
                *(float4*)&nxt[0 * 2048 + tid * 4] = pr0;
                *(float4*)&nxt[1 * 2048 + tid * 4] = pr1;
                *(float4*)&nxt[2 * 2048 + tid * 4] = pr2;
            }
            __syncthreads();   // publish next buffer / guard current buffer reuse
        }

        // ---- Gates + state update (after final chunk barrier: all h reads done) ----
        float hn[4][4];
#pragma unroll
        for (int p = 0; p < 2; p++) {
#pragma unroll
            for (int rr = 0; rr < 4; rr++) {
                float2 z2  = unpack2(az[rr][p]);
                float2 r2  = unpack2(ar[rr][p]);
                float2 h2  = unpack2(ah[rr][p]);
                float2 xh2 = unpack2(axh[rr][p]);
                int c0 = 2 * p, c1 = 2 * p + 1;
                {
                    float z  = sigmoidf_(z2.x + bz[c0]);
                    float r  = sigmoidf_(r2.x + brg[c0]);
                    float hh = tanhf(xh2.x + bxh[c0] + r * (h2.x + brh[c0]));
                    float ho = h_s[(j0 + c0) * TILE_B + r0 + rr];
                    hn[rr][c0] = z * ho + (1.0f - z) * hh;
                }
                {
                    float z  = sigmoidf_(z2.y + bz[c1]);
                    float r  = sigmoidf_(r2.y + brg[c1]);
                    float hh = tanhf(xh2.y + bxh[c1] + r * (h2.y + brh[c1]));
                    float ho = h_s[(j0 + c1) * TILE_B + r0 + rr];
                    hn[rr][c1] = z * ho + (1.0f - z) * hh;
                }
            }
        }

        // h_s[(j0+c)][r0..r0+3] has a unique owner (this thread) for both the
        // ho reads above and these writes; cross-thread reads of h_s were all
        // matmul reads, ordered by the final chunk barrier.
#pragma unroll
        for (int c = 0; c < 4; c++) {
            float4 v = make_float4(hn[0][c], hn[1][c], hn[2][c], hn[3][c]);
            *(float4*)&h_s[(j0 + c) * TILE_B + r0] = v;
        }
        __syncthreads();   // h writes visible before next step's matmul reads
    }

    // ---- Dense + softmax epilogue (h resident in SMEM) ----
    if (tid < TILE_B) {
        const int row = tid;
        float lg[NCLS];
#pragma unroll
        for (int c = 0; c < NCLS; c++) lg[c] = db[c];
        for (int j = 0; j < HID; j++) {
            float hv = h_s[j * TILE_B + row];
#pragma unroll
            for (int c = 0; c < NCLS; c++)
                lg[c] = fmaf(hv, dw[j * NCLS + c], lg[c]);
        }
        float m = lg[0];
#pragma unroll
        for (int c = 1; c < NCLS; c++) m = fmaxf(m, lg[c]);
        float s = 0.0f;
#pragma unroll
        for (int c = 0; c < NCLS; c++) { lg[c] = expf(lg[c] - m); s += lg[c]; }
        float inv = 1.0f / s;
#pragma unroll
        for (int c = 0; c < NCLS; c++)
            out[(size_t)(b0 + row) * NCLS + c] = lg[c] * inv;
    }
}

extern "C" void kernel_launch(void* const* d_in, const int* in_sizes, int n_in,
                              void* d_out, int out_size) {
    const float* x    = (const float*)d_in[0];
    const float* Wk   = (const float*)d_in[1];
    const float* Rk   = (const float*)d_in[2];
    const float* bias = (const float*)d_in[3];
    const float* dw   = (const float*)d_in[4];
    const float* db   = (const float*)d_in[5];
    float* out = (float*)d_out;

    cudaFuncSetAttribute(gru_fused_kernel,
                         cudaFuncAttributeMaxDynamicSharedMemorySize, SM_BYTES);

    gru_fused_kernel<<<BATCH / TILE_B, NTHREADS, SM_BYTES>>>(
        x, Wk, Rk, bias, dw, db, out);
}

// round 6
// speedup vs baseline: 2.6218x; 2.6218x over previous
#include <cuda_runtime.h>
#include <cuda_fp16.h>
#include <cstdint>
#include <math.h>

#define BATCH   16384
#define TSTEPS  28
#define FEAT    28
#define HID     128
#define G3      384
#define NCLS    10

#define TILE_B  32
#define NTH     256
#define NKT     10          // K chunks of 16: kt 0..7 = h (k=j), kt 8,9 = x
#define NBLK    (BATCH / TILE_B)

// B operand in fragment-linear order:
// gB[w(8)][kt(10)][g(4)][nt(2)][lane(32)] : uint4 {bhi0, bhi1, blo0, blo1}
__device__ __align__(16) uint4 gB_frag[8 * NKT * 4 * 2 * 32];

__device__ __forceinline__ uint32_t pack_h2(float a, float b) {
    __half2 p = __floats2half2_rn(a, b);      // a -> low half (k), b -> high (k+1)
    return *reinterpret_cast<uint32_t*>(&p);
}
__device__ __forceinline__ float2 unpack_h2(uint32_t u) {
    __half2 p = *reinterpret_cast<__half2*>(&u);
    return __half22float2(p);
}

__device__ __forceinline__ void mma16816(float* c, uint32_t a0, uint32_t a1,
                                         uint32_t a2, uint32_t a3,
                                         uint32_t b0, uint32_t b1) {
    asm volatile(
        "mma.sync.aligned.m16n8k16.row.col.f32.f16.f16.f32 "
        "{%0,%1,%2,%3}, {%4,%5,%6,%7}, {%8,%9}, {%0,%1,%2,%3};"
        : "+f"(c[0]), "+f"(c[1]), "+f"(c[2]), "+f"(c[3])
        : "r"(a0), "r"(a1), "r"(a2), "r"(a3), "r"(b0), "r"(b1));
}

__device__ __forceinline__ float sig_(float v) { return 1.0f / (1.0f + __expf(-v)); }
__device__ __forceinline__ float tanh_(float v) {
    float t = __expf(-2.0f * fabsf(v));
    float r = (1.0f - t) / (1.0f + t);
    return v < 0.0f ? -r : r;
}

// ---------------------------------------------------------------------------
// Prep: weights -> fragment-linear fp16 hi/lo.
// D[row, n] = sum_k A[row,k] * B[k,n];  n = g*128 + jloc, jloc = 16w + 8nt + gid
// B[k,n]: k<128 -> R rows (h), k in [128,156) -> W rows (x), else 0.
// g: 0=z(col j), 1=r(col 128+j), 2=rh(col 256+j, R only), 3=xh(col 256+j, W only)
// ---------------------------------------------------------------------------
__global__ void prep_B(const float* __restrict__ Rk, const float* __restrict__ Wk) {
    int idx = blockIdx.x * blockDim.x + threadIdx.x;
    if (idx >= 8 * NKT * 4 * 2 * 32) return;
    int lane = idx & 31;
    int nt   = (idx >> 5) & 1;
    int g    = (idx >> 6) & 3;
    int kt   = (idx >> 8) % NKT;
    int w    = (idx >> 8) / NKT;
    int gid  = lane >> 2, tg = lane & 3;

    int jloc = 16 * w + 8 * nt + gid;
    int wcol = (g == 0) ? jloc : (g == 1 ? 128 + jloc : 256 + jloc);
    int k0   = kt * 16 + tg * 2;

    float v[4];
#pragma unroll
    for (int i = 0; i < 4; i++) {
        int k = k0 + (i >> 1) * 8 + (i & 1);
        float val = 0.0f;
        if (k < HID) { if (g != 3) val = Rk[k * G3 + wcol]; }
        else { int f = k - HID; if (f < FEAT && g != 2) val = Wk[f * G3 + wcol]; }
        v[i] = val;
    }
    __half h[4], l[4];
#pragma unroll
    for (int i = 0; i < 4; i++) {
        h[i] = __float2half_rn(v[i]);
        l[i] = __float2half_rn(v[i] - __half2float(h[i]));
    }
    uint4 fr;
    fr.x = pack_h2(__half2float(h[0]), __half2float(h[1]));
    fr.y = pack_h2(__half2float(h[2]), __half2float(h[3]));
    fr.z = pack_h2(__half2float(l[0]), __half2float(l[1]));
    fr.w = pack_h2(__half2float(l[2]), __half2float(l[3]));
    gB_frag[idx] = fr;
}

// ---------------------------------------------------------------------------
// Main fused GRU: persistent per-block scan, HMMA core.
// A frags: Ah[split][kt][mt][lane] uint4 = {a0,a1,a3... order a0,a1,a2,a3}
//   a0:(row gid,   k 2tg)  a1:(row gid+8, k 2tg)
//   a2:(row gid,   k 2tg+8) a3:(row gid+8, k 2tg+8)   rows offset by 16*mt
// ---------------------------------------------------------------------------
__global__ void __launch_bounds__(NTH, 2)
gru_hmma_kernel(const float* __restrict__ x,
                const float* __restrict__ bias,
                const float* __restrict__ dw,
                const float* __restrict__ db,
                float* __restrict__ out)
{
    __shared__ uint4 Ah[2][NKT][2][32];
    __shared__ float hs[TILE_B][HID + 1];

    const int tid  = threadIdx.x;
    const int wid  = tid >> 5;
    const int lane = tid & 31;
    const int gid  = lane >> 2;
    const int tg   = lane & 3;
    const int b0   = blockIdx.x * TILE_B;
    const float* xg = x + (size_t)b0 * (TSTEPS * FEAT);

    // zero A frags
    for (int i = tid; i < 2 * NKT * 2 * 32; i += NTH)
        ((uint4*)Ah)[i] = make_uint4(0, 0, 0, 0);

    // bias -> accumulator-init registers: bp[u][e], u = g*2+nt, cols jloc+e
    float bp[8][2];
#pragma unroll
    for (int g = 0; g < 4; g++)
#pragma unroll
        for (int nt = 0; nt < 2; nt++) {
            int jl = 16 * wid + 8 * nt + 2 * tg;
#pragma unroll
            for (int e = 0; e < 2; e++) {
                int j = jl + e;
                float v;
                if      (g == 0) v = bias[j]       + bias[G3 + j];
                else if (g == 1) v = bias[128 + j] + bias[G3 + 128 + j];
                else if (g == 2) v = bias[G3 + 256 + j];
                else             v = bias[256 + j];
                bp[g * 2 + nt][e] = v;
            }
        }
    __syncthreads();

    // stage x(t=0) frags (kt 8,9). 512 u32 slots per split; 2 slots/thread.
    auto stage_x = [&](int t) {
#pragma unroll
        for (int i = 0; i < 2; i++) {
            int s   = tid * 2 + i;
            int r   = s & 3;
            int ln  = (s >> 2) & 31;
            int mt  = (s >> 7) & 1;
            int kt8 = s >> 8;
            int gd = ln >> 2, tgg = ln & 3;
            int row = mt * 16 + gd + 8 * (r & 1);
            int kl  = kt8 * 16 + tgg * 2 + 8 * (r >> 1);
            float v0 = 0.0f, v1 = 0.0f;
            if (kl < FEAT) {
                const float* p = xg + (size_t)row * (TSTEPS * FEAT) + t * FEAT + kl;
                v0 = p[0];
                if (kl + 1 < FEAT) v1 = p[1];
            }
            __half h0 = __float2half_rn(v0), h1 = __float2half_rn(v1);
            float l0 = v0 - __half2float(h0), l1 = v1 - __half2float(h1);
            ((uint32_t*)&Ah[0][8 + kt8][mt][ln])[r] = pack_h2(v0, v1) /*replaced below*/;
            // pack exact hi halves
            ((uint32_t*)&Ah[0][8 + kt8][mt][ln])[r] =
                (uint32_t)(*(unsigned short*)&h0) | ((uint32_t)(*(unsigned short*)&h1) << 16);
            ((uint32_t*)&Ah[1][8 + kt8][mt][ln])[r] = pack_h2(l0, l1);
        }
    };
    stage_x(0);
    __syncthreads();

    float acc[2][8][4];

    for (int t = 0; t < TSTEPS; t++) {
        // init accumulators with biases
#pragma unroll
        for (int mt = 0; mt < 2; mt++)
#pragma unroll
            for (int u = 0; u < 8; u++) {
                acc[mt][u][0] = bp[u][0]; acc[mt][u][1] = bp[u][1];
                acc[mt][u][2] = bp[u][0]; acc[mt][u][3] = bp[u][1];
            }

        // ---- HMMA mainloop ----
#pragma unroll
        for (int kt = 0; kt < NKT; kt++) {
            uint4 Ah0 = Ah[0][kt][0][lane];
            uint4 Ah1 = Ah[0][kt][1][lane];
            uint4 Al0 = Ah[1][kt][0][lane];
            uint4 Al1 = Ah[1][kt][1][lane];
#pragma unroll
            for (int g = 0; g < 4; g++) {
                if (g == 2 && kt >= 8) continue;   // rh: h rows only
                if (g == 3 && kt <  8) continue;   // xh: x rows only
#pragma unroll
                for (int nt = 0; nt < 2; nt++) {
                    const uint4 B = __ldg(&gB_frag[(((wid * NKT + kt) * 4 + g) * 2 + nt) * 32 + lane]);
                    const int u = g * 2 + nt;
                    mma16816(acc[0][u], Ah0.x, Ah0.y, Ah0.z, Ah0.w, B.x, B.y); // hi*hi
                    mma16816(acc[1][u], Ah1.x, Ah1.y, Ah1.z, Ah1.w, B.x, B.y);
                    mma16816(acc[0][u], Al0.x, Al0.y, Al0.z, Al0.w, B.x, B.y); // lo*hi
                    mma16816(acc[1][u], Al1.x, Al1.y, Al1.z, Al1.w, B.x, B.y);
                    mma16816(acc[0][u], Ah0.x, Ah0.y, Ah0.z, Ah0.w, B.z, B.w); // hi*lo
                    mma16816(acc[1][u], Ah1.x, Ah1.y, Ah1.z, Ah1.w, B.z, B.w);
                }
            }
        }
        __syncthreads();   // all warps done reading A frags

        // ---- epilogue: gates in-register; commit new h frags (kt = wid) ----
#pragma unroll
        for (int mt = 0; mt < 2; mt++) {
            uint4 Hh = Ah[0][wid][mt][lane];
            uint4 Hl = Ah[1][wid][mt][lane];
            const uint32_t hh_[4] = {Hh.x, Hh.y, Hh.z, Hh.w};
            const uint32_t hl_[4] = {Hl.x, Hl.y, Hl.z, Hl.w};
            uint32_t nh[4], nl[4];
#pragma unroll
            for (int r = 0; r < 4; r++) {
                const int nt = r >> 1;
                const int ci = (r & 1) * 2;
                float2 oh = unpack_h2(hh_[r]);
                float2 ol = unpack_h2(hl_[r]);
                float hold[2] = {oh.x + ol.x, oh.y + ol.y};
                float hnew[2];
#pragma unroll
                for (int e = 0; e < 2; e++) {
                    float z  = sig_(acc[mt][0 + nt][ci + e]);
                    float rr = sig_(acc[mt][2 + nt][ci + e]);
                    float hc = tanh_(acc[mt][6 + nt][ci + e] + rr * acc[mt][4 + nt][ci + e]);
                    hnew[e] = z * hold[e] + (1.0f - z) * hc;
                    if (t == TSTEPS - 1) {
                        int row = mt * 16 + gid + 8 * (r & 1);
                        int j   = 16 * wid + 8 * nt + 2 * tg + e;
                        hs[row][j] = hnew[e];
                    }
                }
                __half p0 = __float2half_rn(hnew[0]), p1 = __float2half_rn(hnew[1]);
                float r0 = hnew[0] - __half2float(p0), r1 = hnew[1] - __half2float(p1);
                nh[r] = (uint32_t)(*(unsigned short*)&p0) |
                        ((uint32_t)(*(unsigned short*)&p1) << 16);
                nl[r] = pack_h2(r0, r1);
            }
            Ah[0][wid][mt][lane] = make_uint4(nh[0], nh[1], nh[2], nh[3]);
            Ah[1][wid][mt][lane] = make_uint4(nl[0], nl[1], nl[2], nl[3]);
        }

        if (t < TSTEPS - 1) stage_x(t + 1);
        __syncthreads();   // new A frags visible to all warps
    }

    // ---- dense + softmax ----
    if (tid < TILE_B) {
        const int row = tid;
        float lg[NCLS];
#pragma unroll
        for (int c = 0; c < NCLS; c++) lg[c] = db[c];
        for (int j = 0; j < HID; j++) {
            float hv = hs[row][j];
#pragma unroll
            for (int c = 0; c < NCLS; c++) lg[c] = fmaf(hv, dw[j * NCLS + c], lg[c]);
        }
        float m = lg[0];
#pragma unroll
        for (int c = 1; c < NCLS; c++) m = fmaxf(m, lg[c]);
        float s = 0.0f;
#pragma unroll
        for (int c = 0; c < NCLS; c++) { lg[c] = expf(lg[c] - m); s += lg[c]; }
        float inv = 1.0f / s;
#pragma unroll
        for (int c = 0; c < NCLS; c++)
            out[(size_t)(b0 + row) * NCLS + c] = lg[c] * inv;
    }
}

extern "C" void kernel_launch(void* const* d_in, const int* in_sizes, int n_in,
                              void* d_out, int out_size) {
    const float* x    = (const float*)d_in[0];
    const float* Wk   = (const float*)d_in[1];
    const float* Rk   = (const float*)d_in[2];
    const float* bias = (const float*)d_in[3];
    const float* dw   = (const float*)d_in[4];
    const float* db   = (const float*)d_in[5];
    float* out = (float*)d_out;

    prep_B<<<(8 * NKT * 4 * 2 * 32 + 255) / 256, 256>>>(Rk, Wk);
    gru_hmma_kernel<<<NBLK, NTH>>>(x, bias, dw, db, out);
}